// round 1
// baseline (speedup 1.0000x reference)
#include <cuda_runtime.h>
#include <cuda_bf16.h>

// QuantumCircuit: 16 qubits, RY feature map, 4x (Rot per wire + CNOT chain), <Z0>.
//
// Exact reduction: the Heisenberg-evolved observable A = C^dag Z0 C has support
// only on wires {0,1,2,3} (light cone of Z0 through the CNOT chains is one wire
// per layer). Hence
//     out[b] = <v_b| A |v_b>,   v_b = (c0,s0)x(c1,s1)x(c2,s2)x(c3,s3),
//     c_q = cos(x[b,q]/2), s_q = sin(x[b,q]/2)   (real product state),
// and since v is real, out[b] = v^T M v with M = Re(A), a fixed real symmetric
// 16x16 matrix depending only on params.
//
// Phase 1 (threads 0..15): build W (16x16 complex) = restricted 4-qubit circuit
//   applied to the 16 basis states, all in registers. Qubit q <-> bit (3-q).
// Phase 2 (threads 0..255): M[j][k] = sum_m z_m * Re(conj(W[m][j]) W[m][k]),
//   z_m = +1 if qubit0 bit (mask 8) is 0 else -1.
// Phase 3 (threads 0..511): per-batch quadratic form.

__device__ __forceinline__ float2 cmul(float2 a, float2 b) {
    return make_float2(a.x * b.x - a.y * b.y, a.x * b.y + a.y * b.x);
}
__device__ __forceinline__ float2 cadd(float2 a, float2 b) {
    return make_float2(a.x + b.x, a.y + b.y);
}

__global__ void __launch_bounds__(512, 1)
qc_lightcone_kernel(const float* __restrict__ inputs,   // [B,16]
                    const float* __restrict__ params,   // [4,16,3]
                    float* __restrict__ out,            // [B]
                    int batch) {
    __shared__ float2 Wsh[16][16];   // Wsh[col][amp]
    __shared__ float  Msh[16][16];

    const int t = threadIdx.x;

    // ---------- Phase 1: evolve basis-state columns (registers only) ----------
    if (t < 16) {
        float2 st[16];
#pragma unroll
        for (int m = 0; m < 16; m++)
            st[m] = make_float2(m == t ? 1.0f : 0.0f, 0.0f);

        for (int layer = 0; layer < 4; layer++) {
            // Rot(phi, theta, omega) on wires 0..3
#pragma unroll
            for (int q = 0; q < 4; q++) {
                const float phi = params[layer * 48 + q * 3 + 0];
                const float th  = params[layer * 48 + q * 3 + 1];
                const float om  = params[layer * 48 + q * 3 + 2];
                float c, s, cp, sp, cm, sm;
                sincosf(0.5f * th, &s, &c);
                sincosf(0.5f * (phi + om), &sp, &cp);
                sincosf(0.5f * (phi - om), &sm, &cm);
                // U00 = e^{-i(phi+om)/2} c ; U01 = -e^{+i(phi-om)/2} s
                // U10 = e^{-i(phi-om)/2} s ; U11 = e^{+i(phi+om)/2} c
                const float2 U00 = make_float2( c * cp, -c * sp);
                const float2 U01 = make_float2(-s * cm, -s * sm);
                const float2 U10 = make_float2( s * cm, -s * sm);
                const float2 U11 = make_float2( c * cp,  c * sp);

                const int bit = 8 >> q;   // qubit q <-> bit (3-q)
#pragma unroll
                for (int m = 0; m < 16; m++) {
                    if (m & bit) continue;
                    const float2 a0 = st[m];
                    const float2 a1 = st[m | bit];
                    st[m]       = cadd(cmul(U00, a0), cmul(U01, a1));
                    st[m | bit] = cadd(cmul(U10, a0), cmul(U11, a1));
                }
            }
            // CNOT chain: CNOT(q, q+1) for q = 0,1,2 (pure amplitude permutes)
#pragma unroll
            for (int q = 0; q < 3; q++) {
                const int cb = 8 >> q;
                const int tb = 4 >> q;
#pragma unroll
                for (int m = 0; m < 16; m++) {
                    if ((m & cb) && !(m & tb)) {
                        const float2 tmp = st[m];
                        st[m] = st[m | tb];
                        st[m | tb] = tmp;
                    }
                }
            }
        }
#pragma unroll
        for (int m = 0; m < 16; m++) Wsh[t][m] = st[m];
    }
    __syncthreads();

    // ---------- Phase 2: M = Re(W^dag Z0 W) ----------
    if (t < 256) {
        const int j = t >> 4;
        const int k = t & 15;
        float acc = 0.0f;
#pragma unroll
        for (int m = 0; m < 16; m++) {
            const float z = (m & 8) ? -1.0f : 1.0f;
            acc += z * (Wsh[j][m].x * Wsh[k][m].x + Wsh[j][m].y * Wsh[k][m].y);
        }
        Msh[j][k] = acc;
    }
    __syncthreads();

    // ---------- Phase 3: per-batch quadratic form v^T M v ----------
    for (int b = t; b < batch; b += 512) {
        float c[4], s[4];
#pragma unroll
        for (int q = 0; q < 4; q++)
            sincosf(0.5f * inputs[b * 16 + q], &s[q], &c[q]);

        // v_j: qubit q in |1> iff bit (3-q) of j set -> factor s[q], else c[q]
        float v[16];
#pragma unroll
        for (int j = 0; j < 16; j++) {
            float p = (j & 8) ? s[0] : c[0];
            p      *= (j & 4) ? s[1] : c[1];
            p      *= (j & 2) ? s[2] : c[2];
            p      *= (j & 1) ? s[3] : c[3];
            v[j] = p;
        }

        float acc = 0.0f;
#pragma unroll
        for (int j = 0; j < 16; j++) {
            float row = 0.0f;
#pragma unroll
            for (int k = 0; k < 16; k++)
                row += Msh[j][k] * v[k];
            acc += v[j] * row;
        }
        out[b] = acc;
    }
}

extern "C" void kernel_launch(void* const* d_in, const int* in_sizes, int n_in,
                              void* d_out, int out_size) {
    const float* inputs = (const float*)d_in[0];   // [512,16]
    const float* params = (const float*)d_in[1];   // [4,16,3]
    float* out = (float*)d_out;                    // [512]
    qc_lightcone_kernel<<<1, 512>>>(inputs, params, out, out_size);
}

// round 3
// speedup vs baseline: 1.7472x; 1.7472x over previous
#include <cuda_runtime.h>
#include <cuda_bf16.h>

// QuantumCircuit via exact light-cone reduction: out[b] = v_b^T M v_b
// where M = Re(C^dag Z0 C) restricted to wires {0,1,2,3} (16x16 real symmetric)
// and v_b is the real RY product state on those wires.
//
//  Phase 0: threads 0..15 build gate (layer = t>>2, qubit = t&3) -> shared.
//           (R2 bug was here: params stride is 48 per layer, 3 per qubit.)
//  Phase 1: 256 threads = (col, amp); gates via __shfl_xor butterflies,
//           CNOT chain = one composed-permutation shuffle per layer.
//  Phase 2: 256 threads compute M[j][k] from W in shared.
//  Phase 3: grid=4 CTAs; each CTA's first 128 threads handle one batch element.

__global__ void __launch_bounds__(256, 1)
qc_lightcone3_kernel(const float* __restrict__ inputs,   // [512,16]
                     const float* __restrict__ params,   // [4,16,3]
                     float* __restrict__ out) {          // [512]
    __shared__ float  Ush[16][8];    // gate g: U00.x,.y, U01.x,.y, U10.x,.y, U11.x,.y
    __shared__ float2 Wsh[16][16];   // Wsh[col][amp]
    __shared__ float  Msh[16][16];

    const int t = threadIdx.x;

    // ---------- Phase 0: gate matrices, g = layer*4 + qubit ----------
    if (t < 16) {
        const int layer = t >> 2;
        const int q     = t & 3;
        const float* gp = params + layer * 48 + q * 3;   // [4][16][3] layout
        const float phi = gp[0];
        const float th  = gp[1];
        const float om  = gp[2];
        float c, s, cp, sp, cm, sm;
        __sincosf(0.5f * th, &s, &c);
        __sincosf(0.5f * (phi + om), &sp, &cp);
        __sincosf(0.5f * (phi - om), &sm, &cm);
        // Rot(phi,theta,omega) = RZ(om) RY(th) RZ(phi)
        Ush[t][0] =  c * cp;  Ush[t][1] = -c * sp;   // U00
        Ush[t][2] = -s * cm;  Ush[t][3] = -s * sm;   // U01
        Ush[t][4] =  s * cm;  Ush[t][5] = -s * sm;   // U10
        Ush[t][6] =  c * cp;  Ush[t][7] =  c * sp;   // U11
    }
    __syncthreads();

    // ---------- Phase 1: evolve W columns, one (col, amp) per thread ----------
    // thread t: col = t>>4, amp m = t&15. Two columns per warp; amplitude index
    // = low 4 lane bits, so shfl_xor(bit<16) stays within the column.
    {
        const int m   = t & 15;
        const int col = t >> 4;
        float2 st = make_float2((m == col) ? 1.0f : 0.0f, 0.0f);
        const unsigned FULL = 0xffffffffu;

        for (int layer = 0; layer < 4; layer++) {
#pragma unroll
            for (int q = 0; q < 4; q++) {
                const int g   = layer * 4 + q;
                const int bit = 8 >> q;                  // qubit q <-> bit (3-q)
                const float2 pr = make_float2(__shfl_xor_sync(FULL, st.x, bit),
                                              __shfl_xor_sync(FULL, st.y, bit));
                const bool hi = (m & bit) != 0;
                const float2 a0 = hi ? pr : st;          // amplitude with bit=0
                const float2 a1 = hi ? st : pr;          // amplitude with bit=1
                const float cAx = hi ? Ush[g][4] : Ush[g][0];
                const float cAy = hi ? Ush[g][5] : Ush[g][1];
                const float cBx = hi ? Ush[g][6] : Ush[g][2];
                const float cBy = hi ? Ush[g][7] : Ush[g][3];
                st.x = cAx * a0.x - cAy * a0.y + cBx * a1.x - cBy * a1.y;
                st.y = cAx * a0.y + cAy * a0.x + cBx * a1.y + cBy * a1.x;
            }
            // CNOT chain CNOT(0,1),CNOT(1,2),CNOT(2,3): a'[m] = a[p01(p12(p23(m)))]
            int i = m;
            if (i & 2) i ^= 1;   // p23: ctrl bit 2, tgt bit 1
            if (i & 4) i ^= 2;   // p12
            if (i & 8) i ^= 4;   // p01
            const int srcLane = (t & 16) | i;
            st.x = __shfl_sync(FULL, st.x, srcLane, 32);
            st.y = __shfl_sync(FULL, st.y, srcLane, 32);
        }
        Wsh[col][m] = st;
    }
    __syncthreads();

    // ---------- Phase 2: M[j][k] = sum_m z_m Re(conj(W[m][j]) W[m][k]) ----------
    {
        const int j = t >> 4;
        const int k = t & 15;
        float acc = 0.0f;
#pragma unroll
        for (int m = 0; m < 16; m++) {
            const float z = (m & 8) ? -1.0f : 1.0f;
            acc += z * (Wsh[j][m].x * Wsh[k][m].x + Wsh[j][m].y * Wsh[k][m].y);
        }
        Msh[j][k] = acc;
    }
    __syncthreads();

    // ---------- Phase 3: quadratic form, 128 batch elements per CTA ----------
    if (t < 128) {
        const int b = blockIdx.x * 128 + t;
        float c[4], s[4];
#pragma unroll
        for (int q = 0; q < 4; q++)
            __sincosf(0.5f * inputs[b * 16 + q], &s[q], &c[q]);

        float p01[4], p23[4], v[16];
        p01[0] = c[0] * c[1]; p01[1] = c[0] * s[1];
        p01[2] = s[0] * c[1]; p01[3] = s[0] * s[1];
        p23[0] = c[2] * c[3]; p23[1] = c[2] * s[3];
        p23[2] = s[2] * c[3]; p23[3] = s[2] * s[3];
#pragma unroll
        for (int j = 0; j < 16; j++)
            v[j] = p01[j >> 2] * p23[j & 3];

        float acc = 0.0f;
#pragma unroll
        for (int j = 0; j < 16; j++) {
            float row = 0.0f;
#pragma unroll
            for (int k = 0; k < 16; k++)
                row = fmaf(Msh[j][k], v[k], row);
            acc = fmaf(v[j], row, acc);
        }
        out[b] = acc;
    }
}

extern "C" void kernel_launch(void* const* d_in, const int* in_sizes, int n_in,
                              void* d_out, int out_size) {
    const float* inputs = (const float*)d_in[0];   // [512,16]
    const float* params = (const float*)d_in[1];   // [4,16,3]
    float* out = (float*)d_out;                    // [512]
    qc_lightcone3_kernel<<<4, 256>>>(inputs, params, out);
}

// round 4
// speedup vs baseline: 1.7876x; 1.0232x over previous
#include <cuda_runtime.h>
#include <cuda_bf16.h>

// QuantumCircuit via exact light-cone reduction: out[b] = v_b^T M v_b,
// M = Re(C^dag Z0 C) restricted to wires {0..3}, v_b = real RY product state.
//
// R4 latency restructure:
//  - Batch prep (inputs LDG + sincos + v[16]) hoisted to kernel entry,
//    overlapping Phases 0-2 (it does not depend on params/M).
//  - Ush stored as two float4 halves per gate -> each thread front-batches
//    its 16 needed coefficient quads as LDS.128 before the butterfly chain.
//  - Last layer's CNOT permutation folded into the Wsh write index.
//  - Phase 2 / Phase 3 read W and M as float4 (LDS.128).

__global__ void __launch_bounds__(256, 1)
qc_lightcone4_kernel(const float* __restrict__ inputs,   // [512,16]
                     const float* __restrict__ params,   // [4,16,3]
                     float* __restrict__ out) {          // [512]
    __shared__ float4 Ush[16][2];    // gate g: [0]=(U00.x,U00.y,U01.x,U01.y)
                                     //         [1]=(U10.x,U10.y,U11.x,U11.y)
    __shared__ float2 Wsh[16][16];   // Wsh[col][amp]
    __shared__ float  Msh[16][16];

    const int t = threadIdx.x;

    // ---------- Batch prep (independent of params): overlap with Phases 0-2 ----
    float v[16];
    if (t < 128) {
        const int b = blockIdx.x * 128 + t;
        const float4 x = *(const float4*)(inputs + b * 16);   // wires 0..3
        float c0, s0, c1, s1, c2, s2, c3, s3;
        __sincosf(0.5f * x.x, &s0, &c0);
        __sincosf(0.5f * x.y, &s1, &c1);
        __sincosf(0.5f * x.z, &s2, &c2);
        __sincosf(0.5f * x.w, &s3, &c3);
        float p01[4], p23[4];
        p01[0] = c0 * c1; p01[1] = c0 * s1; p01[2] = s0 * c1; p01[3] = s0 * s1;
        p23[0] = c2 * c3; p23[1] = c2 * s3; p23[2] = s2 * c3; p23[3] = s2 * s3;
#pragma unroll
        for (int j = 0; j < 16; j++)
            v[j] = p01[j >> 2] * p23[j & 3];
    }

    // ---------- Phase 0: gate matrices, gate g = layer*4 + qubit ----------
    if (t < 16) {
        const int layer = t >> 2;
        const int q     = t & 3;
        const float* gp = params + layer * 48 + q * 3;   // [4][16][3]
        const float phi = gp[0];
        const float th  = gp[1];
        const float om  = gp[2];
        float c, s, cp, sp, cm, sm;
        __sincosf(0.5f * th, &s, &c);
        __sincosf(0.5f * (phi + om), &sp, &cp);
        __sincosf(0.5f * (phi - om), &sm, &cm);
        // Rot = RZ(om) RY(th) RZ(phi)
        Ush[t][0] = make_float4( c * cp, -c * sp, -s * cm, -s * sm); // U00,U01
        Ush[t][1] = make_float4( s * cm, -s * sm,  c * cp,  c * sp); // U10,U11
    }
    __syncthreads();

    // ---------- Phase 1: evolve W columns; thread t = (col = t>>4, m = t&15) --
    {
        const int m   = t & 15;
        const int col = t >> 4;
        const unsigned FULL = 0xffffffffu;

        // Front-batch all 16 coefficient quads (selection is thread-constant).
        float4 coef[16];
#pragma unroll
        for (int g = 0; g < 16; g++) {
            const int bit = 8 >> (g & 3);
            coef[g] = Ush[g][(m & bit) ? 1 : 0];
        }

        float2 st = make_float2((m == col) ? 1.0f : 0.0f, 0.0f);

#pragma unroll
        for (int layer = 0; layer < 4; layer++) {
#pragma unroll
            for (int q = 0; q < 4; q++) {
                const int g   = layer * 4 + q;
                const int bit = 8 >> q;
                const float2 pr = make_float2(__shfl_xor_sync(FULL, st.x, bit),
                                              __shfl_xor_sync(FULL, st.y, bit));
                const bool hi = (m & bit) != 0;
                const float2 a0 = hi ? pr : st;       // amp with bit=0
                const float2 a1 = hi ? st : pr;       // amp with bit=1
                const float4 u = coef[g];             // (cAx,cAy,cBx,cBy)
                st.x = u.x * a0.x - u.y * a0.y + u.z * a1.x - u.w * a1.y;
                st.y = u.x * a0.y + u.y * a0.x + u.z * a1.y + u.w * a1.x;
            }
            if (layer < 3) {
                // CNOT chain as one composed permutation: a'[m] = a[src(m)]
                int i = m;
                if (i & 2) i ^= 1;
                if (i & 4) i ^= 2;
                if (i & 8) i ^= 4;
                const int srcLane = (t & 16) | i;
                st.x = __shfl_sync(FULL, st.x, srcLane, 32);
                st.y = __shfl_sync(FULL, st.y, srcLane, 32);
            }
        }
        // Fold last layer's permutation into the write index: write to inv(m).
        int i = m;
        if (i & 8) i ^= 4;
        if (i & 4) i ^= 2;
        if (i & 2) i ^= 1;
        Wsh[col][i] = st;
    }
    __syncthreads();

    // ---------- Phase 2: M[j][k] = sum_m z_m Re(conj(W[m][j]) W[m][k]) --------
    {
        const int j = t >> 4;
        const int k = t & 15;
        const float4* Wj = (const float4*)&Wsh[j][0];   // 8 quads = 16 float2
        const float4* Wk = (const float4*)&Wsh[k][0];
        float accp = 0.0f, accm = 0.0f;                  // m<8 plus, m>=8 minus
#pragma unroll
        for (int mm = 0; mm < 8; mm++) {
            const float4 a = Wj[mm];
            const float4 b = Wk[mm];
            const float d = a.x * b.x + a.y * b.y + a.z * b.z + a.w * b.w;
            if (mm < 4) accp += d; else accm += d;
        }
        Msh[j][k] = accp - accm;
    }
    __syncthreads();

    // ---------- Phase 3: quadratic form (v already in registers) -------------
    if (t < 128) {
        const int b = blockIdx.x * 128 + t;
        const float4* M4 = (const float4*)Msh;
        float acc = 0.0f;
#pragma unroll
        for (int j = 0; j < 16; j++) {
            float row = 0.0f;
#pragma unroll
            for (int kk = 0; kk < 4; kk++) {
                const float4 mrow = M4[j * 4 + kk];
                row = fmaf(mrow.x, v[kk * 4 + 0], row);
                row = fmaf(mrow.y, v[kk * 4 + 1], row);
                row = fmaf(mrow.z, v[kk * 4 + 2], row);
                row = fmaf(mrow.w, v[kk * 4 + 3], row);
            }
            acc = fmaf(v[j], row, acc);
        }
        out[b] = acc;
    }
}

extern "C" void kernel_launch(void* const* d_in, const int* in_sizes, int n_in,
                              void* d_out, int out_size) {
    const float* inputs = (const float*)d_in[0];   // [512,16]
    const float* params = (const float*)d_in[1];   // [4,16,3]
    float* out = (float*)d_out;                    // [512]
    qc_lightcone4_kernel<<<4, 256>>>(inputs, params, out);
}